// round 16
// baseline (speedup 1.0000x reference)
#include <cuda_runtime.h>
#include <cuda_fp16.h>
#include <cstdint>

// ---------------------------------------------------------------------------
// KAGNMoE round 15: conv epilogue staged through smem.
//   Old epilogue: 64 scattered STG.32/thread (32 sectors per warp-store).
//   New: conflict-free STS.32 into [oc*516 + row*16 + px] staging (66KB,
//   reuses the dead double buffers), then 16 LDS.128 + 16 coalesced STG.128.
//   Everything else identical to round 14 (172.3us; conv 97.8, tensor 54.7%).
// ---------------------------------------------------------------------------

#define NB 16
#define CI 32
#define HH 192
#define WW 192
#define HW (HH * WW)
#define GC96 96
#define NE 8

// channel-last basis scratch: [n][h][w][96] fp16, ~113 MB
__device__ __half g_scratch[(size_t)NB * HH * WW * GC96];
// weights fp16: [ch6][tap9][ng4][kk2][row8][col8] halves (27648 total)
__device__ __half w_prep[6 * 4608];
__device__ float gate_mean_s[NB * CI];
__device__ float s_scale_s[NB];
__device__ float bias_g[9 * CI];

__device__ __forceinline__ float silu_f(float v) { return v / (1.0f + expf(-v)); }
__device__ __forceinline__ float tanh_fast(float v) {
    float r; asm("tanh.approx.f32 %0, %1;" : "=f"(r) : "f"(v)); return r;
}
__device__ __forceinline__ float silu_fast(float v) {
    return __fdividef(v, 1.0f + __expf(-v));
}
__device__ __forceinline__ void mma_f16(float* d, unsigned a0, unsigned a1,
                                        unsigned a2, unsigned a3,
                                        unsigned b0, unsigned b1) {
    asm("mma.sync.aligned.m16n8k16.row.col.f32.f16.f16.f32 "
        "{%0,%1,%2,%3}, {%4,%5,%6,%7}, {%8,%9}, {%0,%1,%2,%3};"
        : "+f"(d[0]), "+f"(d[1]), "+f"(d[2]), "+f"(d[3])
        : "r"(a0), "r"(a1), "r"(a2), "r"(a3), "r"(b0), "r"(b1));
}
__device__ __forceinline__ void cp16(uint32_t dst, const void* src, int sz) {
    asm volatile("cp.async.ca.shared.global [%0], [%1], 16, %2;"
                 :: "r"(dst), "l"(src), "r"(sz));
}
#define CP_COMMIT() asm volatile("cp.async.commit_group;")
#define CP_WAIT(n)  asm volatile("cp.async.wait_group %0;" :: "n"(n))

__device__ float cv_sq(const float* v) {
    float m = 0.0f;
    #pragma unroll
    for (int i = 0; i < NE; ++i) m += v[i];
    m *= (1.0f / NE);
    float var = 0.0f;
    #pragma unroll
    for (int i = 0; i < NE; ++i) { float d = v[i] - m; var += d * d; }
    var *= (1.0f / (NE - 1));
    return var / (m * m + 1e-10f);
}

// ---------------------------------------------------------------------------
// K0: per-(n,ci) spatial mean of x.
// EXACT scalar strided structure -- summation order is part of the loss's
// top-2 index correctness contract. Do not reorder.
// ---------------------------------------------------------------------------
__global__ void gate_mean_kernel(const float* __restrict__ x) {
    const int b = blockIdx.x;
    const float* xp = x + (size_t)b * HW;
    float s = 0.0f;
    for (int i = threadIdx.x; i < HW; i += 256) s += xp[i];
    __shared__ float sh[8];
    #pragma unroll
    for (int o = 16; o > 0; o >>= 1) s += __shfl_down_sync(0xffffffffu, s, o);
    if ((threadIdx.x & 31) == 0) sh[threadIdx.x >> 5] = s;
    __syncthreads();
    if (threadIdx.x < 8) {
        s = sh[threadIdx.x];
        #pragma unroll
        for (int o = 4; o > 0; o >>= 1) s += __shfl_down_sync(0xffu, s, o);
        if (threadIdx.x == 0) gate_mean_s[b] = s * (1.0f / 36864.0f);
    }
}

// ---------------------------------------------------------------------------
// K1: prep = fp16 weights (blocks 0..107) + bias (108) + gating (109).
// ---------------------------------------------------------------------------
__global__ void prep_kernel(const float* __restrict__ W,
                            const float* __restrict__ wg,
                            float* __restrict__ d_out, int loss_idx) {
    if (blockIdx.x < 108) {
        int j = blockIdx.x * 256 + threadIdx.x;    // < 27648 halves
        int ch = j / 4608;
        int jj = j - ch * 4608;
        int tap = jj / 512;
        int r0 = jj - tap * 512;
        int ng = r0 >> 7;
        int r1 = r0 & 127;
        int kk = r1 >> 6;
        int r2 = r1 & 63;
        int row = r2 >> 3;
        int col = r2 & 7;
        int oc = ng * 8 + row;
        int cc = kk * 8 + col;
        w_prep[j] = __float2half_rn(
            W[((size_t)oc * 128 + 32 + ch * 16 + cc) * 9 + tap]);
        return;
    }
    if (blockIdx.x == 108) {
        int oc = threadIdx.x;
        if (oc >= 32) return;
        float S[9];
        #pragma unroll
        for (int k = 0; k < 9; ++k) S[k] = 0.0f;
        for (int ci = 0; ci < 32; ++ci)
            #pragma unroll
            for (int k = 0; k < 9; ++k)
                S[k] += W[((size_t)oc * 128 + ci) * 9 + k];
        const float c0 = silu_f(1.0f);
        #pragma unroll
        for (int ry = 0; ry < 3; ++ry)
            #pragma unroll
            for (int cx = 0; cx < 3; ++cx) {
                float b = 0.0f;
                #pragma unroll
                for (int kh = 0; kh < 3; ++kh) {
                    if ((ry == 0 && kh == 0) || (ry == 2 && kh == 2)) continue;
                    #pragma unroll
                    for (int kw = 0; kw < 3; ++kw) {
                        if ((cx == 0 && kw == 0) || (cx == 2 && kw == 2)) continue;
                        b += S[kh * 3 + kw];
                    }
                }
                bias_g[(ry * 3 + cx) * CI + oc] = b * c0;
            }
        return;
    }
    // ---- block 109: gating
    __shared__ float sg0[NB], sg1[NB];
    __shared__ int si0[NB], si1[NB];
    int t = threadIdx.x;
    if (t < NB) {
        float l[NE];
        #pragma unroll
        for (int e = 0; e < NE; ++e) {
            float a = 0.0f;
            #pragma unroll
            for (int c = 0; c < CI; ++c) a += gate_mean_s[t * CI + c] * wg[c * NE + e];
            l[e] = a;
        }
        float m = l[0];
        #pragma unroll
        for (int e = 1; e < NE; ++e) m = fmaxf(m, l[e]);
        float p[NE]; float sum = 0.0f;
        #pragma unroll
        for (int e = 0; e < NE; ++e) { p[e] = expf(l[e] - m); sum += p[e]; }
        float inv = 1.0f / sum;
        #pragma unroll
        for (int e = 0; e < NE; ++e) p[e] *= inv;
        int i0 = 0; float v0 = p[0];
        #pragma unroll
        for (int e = 1; e < NE; ++e) if (p[e] > v0) { v0 = p[e]; i0 = e; }
        int i1 = -1; float v1 = -1.0f;
        #pragma unroll
        for (int e = 0; e < NE; ++e) if (e != i0 && p[e] > v1) { v1 = p[e]; i1 = e; }
        float invS = 1.0f / (v0 + v1 + 1e-6f);
        sg0[t] = v0 * invS;
        sg1[t] = v1 * invS;
        si0[t] = i0;
        si1[t] = i1;
        s_scale_s[t] = (v0 + v1) * invS;
    }
    __syncthreads();
    if (t == 0) {
        float imp[NE] = {0}, ld[NE] = {0};
        for (int n = 0; n < NB; ++n) {
            imp[si0[n]] += sg0[n];
            imp[si1[n]] += sg1[n];
            ld[si0[n]] += 1.0f;
            ld[si1[n]] += 1.0f;
        }
        d_out[loss_idx] = 0.01f * (cv_sq(imp) + cv_sq(ld));
    }
}

// ---------------------------------------------------------------------------
// K2: basis, fast-math, fp16 output (unchanged; ~42us).
// ---------------------------------------------------------------------------
__global__ __launch_bounds__(256) void basis_kernel(const float* __restrict__ x,
                                                    const float* __restrict__ bw) {
    const int n = blockIdx.z, h = blockIdx.y, w0 = blockIdx.x * 64;
    const int tid = threadIdx.x;
    const int cisub = tid >> 6;
    const int pix = tid & 63;

    __shared__ __align__(16) __half st[64 * 104];
    const float beta2 = 2.25f * bw[1];
    const float beta3 = (300.0f / 9.0f) * bw[2];

    #pragma unroll
    for (int it = 0; it < 8; ++it) {
        const int ci = it * 4 + cisub;
        float v = x[((size_t)(n * CI + ci) * HH + h) * WW + w0 + pix];
        float t = tanh_fast(v);
        float p2 = t * t - beta2;
        float p3 = t * p2 - beta3 * t;
        st[pix * 104 + ci]      = __float2half_rn(silu_fast(t));
        st[pix * 104 + 32 + ci] = __float2half_rn(silu_fast(p2));
        st[pix * 104 + 64 + ci] = __float2half_rn(silu_fast(p3));
    }
    __syncthreads();

    uint4* gout4 = reinterpret_cast<uint4*>(
        g_scratch + ((size_t)(n * HH + h) * WW + w0) * GC96);
    const uint4* st4 = reinterpret_cast<const uint4*>(st);
    #pragma unroll
    for (int it = 0; it < 3; ++it) {
        int f4 = it * 256 + tid;
        int p = f4 / 12, c4 = f4 - p * 12;
        gout4[f4] = st4[p * 13 + c4];
    }
}

// ---------------------------------------------------------------------------
// K3: conv, 16x32 tile, 4 rows/warp, kw-major A-reuse; smem-staged epilogue.
// Buffers: 2 x 38592B; epilogue staging [oc*516 + row*16 + px] = 66032B
// aliases both buffers after the final compute barrier.
// ---------------------------------------------------------------------------
#define BUFFB 38592
#define WOFFB 29376

__global__ __launch_bounds__(256, 2) void conv_kernel(float* __restrict__ out) {
    extern __shared__ char smc[];
    const int n = blockIdx.z;
    const int x0 = blockIdx.x * 16;
    const int y0 = blockIdx.y * 32;
    const int tid = threadIdx.x;
    const int lane = tid & 31;
    const int wid = tid >> 5;
    const int g = lane >> 2;
    const int t = lane & 3;

    uint32_t smbase;
    asm("{ .reg .u64 tt; cvta.to.shared.u64 tt, %1; cvt.u32.u64 %0, tt; }"
        : "=r"(smbase) : "l"(smc));
    const uint32_t alane = (uint32_t)(lane & 15) * 48u + (uint32_t)(lane >> 4) * 16u;

    float acc[4][4][4];
    #pragma unroll
    for (int b = 0; b < 4; ++b)
        #pragma unroll
        for (int c = 0; c < 4; ++c)
            #pragma unroll
            for (int d = 0; d < 4; ++d) acc[b][c][d] = 0.0f;

    // ---- prefetch: 34*18*2 = 1224 g-cp16 + 576 w-cp16
    auto prefetch = [&](int ch, int buf) {
        uint32_t base = smbase + (uint32_t)buf * BUFFB;
        for (int i = tid; i < 1224; i += 256) {
            int plane = i & 1;
            int pos = i >> 1;
            int r = pos / 18;
            int c = pos - r * 18;
            int gy = y0 - 1 + r, gx = x0 - 1 + c;
            int ok = ((unsigned)gy < 192u) & ((unsigned)gx < 192u);
            int cgy = ok ? gy : 0, cgx = ok ? gx : 0;
            const __half* src = g_scratch + (((size_t)n * HH + cgy) * WW + cgx) * GC96
                                + ch * 16 + plane * 8;
            uint32_t dst = base + (uint32_t)(r * 864 + c * 48 + plane * 16);
            cp16(dst, src, ok ? 16 : 0);
        }
        const __half* wsrc = w_prep + ch * 4608;
        uint32_t wdst = base + WOFFB;
        for (int i = tid; i < 576; i += 256)
            cp16(wdst + (uint32_t)i * 16u, wsrc + i * 8, 16);
    };

    prefetch(0, 0); CP_COMMIT();

    for (int ch = 0; ch < 6; ++ch) {
        if (ch < 5) {
            prefetch(ch + 1, (ch + 1) & 1);
            CP_COMMIT();
            CP_WAIT(1);
        } else {
            CP_WAIT(0);
        }
        __syncthreads();

        const int buf = ch & 1;
        const uint32_t abase = smbase + (uint32_t)buf * BUFFB + alane;
        const uint32_t wbase = smbase + (uint32_t)buf * BUFFB + WOFFB
                               + (uint32_t)lane * 16u;

        #pragma unroll
        for (int kw = 0; kw < 3; ++kw) {
            unsigned A[6][4];
            #pragma unroll
            for (int j = 0; j < 6; ++j) {
                uint32_t addr = abase + (uint32_t)((4 * wid + j) * 864 + kw * 48);
                asm volatile("ldmatrix.sync.aligned.m8n8.x4.shared.b16 "
                             "{%0,%1,%2,%3}, [%4];"
                             : "=r"(A[j][0]), "=r"(A[j][1]),
                               "=r"(A[j][2]), "=r"(A[j][3])
                             : "r"(addr));
            }
            #pragma unroll
            for (int kh = 0; kh < 3; ++kh) {
                const int tap = kh * 3 + kw;
                unsigned b0[4], b1[4];
                #pragma unroll
                for (int p = 0; p < 2; ++p) {
                    uint32_t waddr = wbase + (uint32_t)(tap * 1024 + p * 512);
                    asm volatile("ldmatrix.sync.aligned.m8n8.x4.shared.b16 "
                                 "{%0,%1,%2,%3}, [%4];"
                                 : "=r"(b0[2 * p]), "=r"(b1[2 * p]),
                                   "=r"(b0[2 * p + 1]), "=r"(b1[2 * p + 1])
                                 : "r"(waddr));
                }
                #pragma unroll
                for (int mrow = 0; mrow < 4; ++mrow) {
                    const int j = mrow + kh;
                    #pragma unroll
                    for (int nc = 0; nc < 4; ++nc)
                        mma_f16(acc[mrow][nc], A[j][0], A[j][1], A[j][2], A[j][3],
                                b0[nc], b1[nc]);
                }
            }
        }
        __syncthreads();   // protect buf from next iteration's prefetch
    }

    // ---- epilogue: bias + scale -> smem staging -> coalesced float4 stores
    // staging layout: saddr = oc*516 + row*16 + px (floats); conflict-free STS
    float* sout = reinterpret_cast<float*>(smc);
    const float s = s_scale_s[n];
    #pragma unroll
    for (int mrow = 0; mrow < 4; ++mrow) {
        const int row = 4 * wid + mrow;
        const int y = y0 + row;
        const int ry = (y == 0) ? 0 : ((y == HH - 1) ? 2 : 1);
        #pragma unroll
        for (int nc = 0; nc < 4; ++nc) {
            #pragma unroll
            for (int e = 0; e < 4; ++e) {
                const int px = g + ((e >= 2) ? 8 : 0);
                const int oc = 8 * nc + 2 * t + (e & 1);
                const int xx = x0 + px;
                const int cx = (xx == 0) ? 0 : ((xx == WW - 1) ? 2 : 1);
                sout[oc * 516 + row * 16 + px] =
                    (acc[mrow][nc][e] + bias_g[(ry * 3 + cx) * CI + oc]) * s;
            }
        }
    }
    __syncthreads();

    // drain: 4096 float4 = 16 per thread; 64B contiguous per (oc,row)
    #pragma unroll
    for (int it = 0; it < 16; ++it) {
        int j = it * 256 + tid;
        int oc = j >> 7;              // 4 float4 per (oc,row), 32 rows
        int rq = j & 127;
        int row = rq >> 2;
        int q = rq & 3;
        float4 v = *reinterpret_cast<const float4*>(sout + oc * 516 + row * 16 + q * 4);
        *reinterpret_cast<float4*>(
            out + ((size_t)(n * CI + oc) * HH + y0 + row) * WW + x0 + q * 4) = v;
    }
}

// ---------------------------------------------------------------------------
extern "C" void kernel_launch(void* const* d_in, const int* in_sizes, int n_in,
                              void* d_out, int out_size) {
    const float* x  = (const float*)d_in[0];
    const float* wg = (const float*)d_in[1];
    const float* W  = (const float*)d_in[2];
    const float* bw = (const float*)d_in[3];
    float* out = (float*)d_out;
    const int loss_idx = out_size - 1;

    cudaFuncSetAttribute(conv_kernel, cudaFuncAttributeMaxDynamicSharedMemorySize,
                         BUFFB * 2);

    gate_mean_kernel<<<NB * CI, 256>>>(x);
    prep_kernel<<<110, 256>>>(W, wg, out, loss_idx);
    basis_kernel<<<dim3(3, 192, 16), 256>>>(x, bw);
    conv_kernel<<<dim3(12, 6, 16), 256, BUFFB * 2>>>(out);
}